// round 2
// baseline (speedup 1.0000x reference)
#include <cuda_runtime.h>
#include <cstdint>

// ---------------------------------------------------------------------------
// voltageNN: 2-layer LSTM (H=256, proj P=1, in=1, T=1000) + MLP head, B=16384.
// Fully fused: per-warp scalar recurrence, weights in registers, layer-0
// output staged in smem, MLP-head GEMV accumulated in-loop (W1 pre-transposed).
// ---------------------------------------------------------------------------

#define HID   256
#define TLEN  1000
#define FULLM 0xffffffffu

// Packed weights: per hidden unit k, gate order (i, f, o, g) in (x,y,z,w).
// i/f/o components pre-scaled by 0.5 (sigmoid(x) = 0.5*tanh(0.5x)+0.5).
__device__ float4 g_wx[2][HID];   // input weights  (Wih)
__device__ float4 g_wh[2][HID];   // recurrent weights (Whh)
__device__ float4 g_wb[2][HID];   // bias (bih+bhh)
__device__ float  g_wr[2][HID];   // projection Whr
__device__ float  g_w1t[TLEN * 128];  // W1 transposed + padded: [t][j], j<128
__device__ float  g_b1p[128];
__device__ float  g_w2p[128];

__device__ __forceinline__ float tanh_fast(float x) {
    float y;
    asm("tanh.approx.f32 %0, %1;" : "=f"(y) : "f"(x));
    return y;
}

// ---------------------------------------------------------------------------
// Prep kernel: pack/transpose weights. grid = TLEN+1 blocks x 128 threads.
// ---------------------------------------------------------------------------
__global__ void prep_kernel(
    const float* __restrict__ Wih0, const float* __restrict__ Whh0,
    const float* __restrict__ bih0, const float* __restrict__ bhh0,
    const float* __restrict__ Whr0,
    const float* __restrict__ Wih1, const float* __restrict__ Whh1,
    const float* __restrict__ bih1, const float* __restrict__ bhh1,
    const float* __restrict__ Whr1,
    const float* __restrict__ W1,  const float* __restrict__ b1,
    const float* __restrict__ W2)
{
    int tid = threadIdx.x;
    int blk = blockIdx.x;
    if (blk < TLEN) {
        // W1 is (100, 1000) row-major; build W1T[t][j] with zero pad to 128.
        int t = blk;
        int j = tid;  // 0..127
        g_w1t[t * 128 + j] = (j < 100) ? W1[j * TLEN + t] : 0.0f;
        return;
    }
    // blk == TLEN: pack LSTM weights + head vectors
    for (int i = tid; i < 2 * HID; i += 128) {
        int layer = i >> 8;
        int k = i & (HID - 1);
        const float* Wih = layer ? Wih1 : Wih0;
        const float* Whh = layer ? Whh1 : Whh0;
        const float* bih = layer ? bih1 : bih0;
        const float* bhh = layer ? bhh1 : bhh0;
        const float* Whr = layer ? Whr1 : Whr0;
        // stacked gate rows in source: i [0,256), f [256,512), g [512,768), o [768,1024)
        float4 wx, wh, wb;
        wx.x = 0.5f * Wih[k];
        wx.y = 0.5f * Wih[256 + k];
        wx.z = 0.5f * Wih[768 + k];
        wx.w =        Wih[512 + k];
        wh.x = 0.5f * Whh[k];
        wh.y = 0.5f * Whh[256 + k];
        wh.z = 0.5f * Whh[768 + k];
        wh.w =        Whh[512 + k];
        wb.x = 0.5f * (bih[k]       + bhh[k]);
        wb.y = 0.5f * (bih[256 + k] + bhh[256 + k]);
        wb.z = 0.5f * (bih[768 + k] + bhh[768 + k]);
        wb.w =        (bih[512 + k] + bhh[512 + k]);
        g_wx[layer][k] = wx;
        g_wh[layer][k] = wh;
        g_wb[layer][k] = wb;
        g_wr[layer][k] = Whr[k];
    }
    if (tid < 128) {
        g_b1p[tid] = (tid < 100) ? b1[tid] : 0.0f;
        g_w2p[tid] = (tid < 100) ? W2[tid] : 0.0f;
    }
}

// ---------------------------------------------------------------------------
// One LSTM step for 8 hidden units/lane; returns projected scalar h (all lanes).
// ---------------------------------------------------------------------------
__device__ __forceinline__ float lstm_step(
    float xv, float h,
    const float4* wx, const float4* wh, const float4* wb,
    const float* wr, float* c)
{
    float part = 0.0f;
#pragma unroll
    for (int m = 0; m < 8; m++) {
        float pi = fmaf(h, wh[m].x, wb[m].x); pi = fmaf(xv, wx[m].x, pi);
        float pf = fmaf(h, wh[m].y, wb[m].y); pf = fmaf(xv, wx[m].y, pf);
        float po = fmaf(h, wh[m].z, wb[m].z); po = fmaf(xv, wx[m].z, po);
        float pg = fmaf(h, wh[m].w, wb[m].w); pg = fmaf(xv, wx[m].w, pg);
        float gi = fmaf(tanh_fast(pi), 0.5f, 0.5f);
        float gf = fmaf(tanh_fast(pf), 0.5f, 0.5f);
        float go = fmaf(tanh_fast(po), 0.5f, 0.5f);
        float gg = tanh_fast(pg);
        float cm = fmaf(gf, c[m], gi * gg);
        c[m] = cm;
        part = fmaf(go * tanh_fast(cm), wr[m], part);
    }
#pragma unroll
    for (int s = 16; s; s >>= 1)
        part += __shfl_xor_sync(FULLM, part, s);
    return part;
}

// ---------------------------------------------------------------------------
// Main kernel: 1 warp per batch element, 4 warps/block.
// ---------------------------------------------------------------------------
__global__ __launch_bounds__(128, 3) void lstm_kernel(
    const float* __restrict__ x,
    const float* __restrict__ b2,
    float* __restrict__ out)
{
    __shared__ float sbuf[4][TLEN + 8];

    int warp = threadIdx.x >> 5;
    int lane = threadIdx.x & 31;
    int b = blockIdx.x * 4 + warp;
    const float* xb = x + (size_t)b * TLEN;

    float4 wx[8], wh[8], wb[8];
    float  wr[8], c[8];

    // ---------------- pass 1: layer 0 ----------------
#pragma unroll
    for (int m = 0; m < 8; m++) {
        int k = lane + 32 * m;
        wx[m] = g_wx[0][k]; wh[m] = g_wh[0][k]; wb[m] = g_wb[0][k];
        wr[m] = g_wr[0][k]; c[m] = 0.0f;
    }
    float h = 0.0f;
    float xr = 0.0f;
    for (int t = 0; t < TLEN; t++) {
        if ((t & 31) == 0) {
            int ti = t + lane;
            xr = xb[(ti < TLEN) ? ti : (TLEN - 1)];
        }
        float xv = __shfl_sync(FULLM, xr, t & 31);
        h = lstm_step(xv, h, wx, wh, wb, wr, c);
        if (lane == 0) sbuf[warp][t] = h;
    }
    __syncwarp();

    // ---------------- pass 2: layer 1 + fused head ----------------
#pragma unroll
    for (int m = 0; m < 8; m++) {
        int k = lane + 32 * m;
        wx[m] = g_wx[1][k]; wh[m] = g_wh[1][k]; wb[m] = g_wb[1][k];
        wr[m] = g_wr[1][k]; c[m] = 0.0f;
    }
    h = 0.0f;
    float a0 = 0.0f, a1 = 0.0f, a2 = 0.0f, a3 = 0.0f;
    for (int t = 0; t < TLEN; t++) {
        float xv = sbuf[warp][t];
        h = lstm_step(xv, h, wx, wh, wb, wr, c);
        const float* wrow = g_w1t + t * 128;
        a0 = fmaf(h, wrow[lane     ], a0);
        a1 = fmaf(h, wrow[lane + 32], a1);
        a2 = fmaf(h, wrow[lane + 64], a2);
        a3 = fmaf(h, wrow[lane + 96], a3);
    }

    // head: out = relu(acc + b1) @ W2 + b2   (padding is zero -> no effect)
    float s = fmaxf(a0 + g_b1p[lane     ], 0.0f) * g_w2p[lane     ]
            + fmaxf(a1 + g_b1p[lane + 32], 0.0f) * g_w2p[lane + 32]
            + fmaxf(a2 + g_b1p[lane + 64], 0.0f) * g_w2p[lane + 64]
            + fmaxf(a3 + g_b1p[lane + 96], 0.0f) * g_w2p[lane + 96];
#pragma unroll
    for (int sf = 16; sf; sf >>= 1)
        s += __shfl_xor_sync(FULLM, s, sf);
    if (lane == 0) out[b] = s + b2[0];
}

// ---------------------------------------------------------------------------
// kernel_launch
// ---------------------------------------------------------------------------
extern "C" void kernel_launch(void* const* d_in, const int* in_sizes, int n_in,
                              void* d_out, int out_size)
{
    const float* x    = (const float*)d_in[0];
    const float* Wih0 = (const float*)d_in[1];
    const float* Whh0 = (const float*)d_in[2];
    const float* bih0 = (const float*)d_in[3];
    const float* bhh0 = (const float*)d_in[4];
    const float* Whr0 = (const float*)d_in[5];
    const float* Wih1 = (const float*)d_in[6];
    const float* Whh1 = (const float*)d_in[7];
    const float* bih1 = (const float*)d_in[8];
    const float* bhh1 = (const float*)d_in[9];
    const float* Whr1 = (const float*)d_in[10];
    const float* W1   = (const float*)d_in[11];
    const float* b1   = (const float*)d_in[12];
    const float* W2   = (const float*)d_in[13];
    const float* b2   = (const float*)d_in[14];
    float* out = (float*)d_out;

    int B = in_sizes[0] / TLEN;   // 16384

    prep_kernel<<<TLEN + 1, 128>>>(Wih0, Whh0, bih0, bhh0, Whr0,
                                   Wih1, Whh1, bih1, bhh1, Whr1,
                                   W1, b1, W2);
    lstm_kernel<<<B / 4, 128>>>(x, b2, out);
}